// round 8
// baseline (speedup 1.0000x reference)
#include <cuda_runtime.h>

// out[b][f][t][v] = elu(diag[b,v,t] * Wh[b,v,t,f])
//   Wh[b,v,t,f] = sum_c x[b,c,t,v] * W[c,f]      <-- mma.sync bf16 3-pass split
//   s1[v] = Wh[v,:]·a1 ; s2[v] = Wh[v,:]·a2       (per b,t)
//   diag[v] = num(v) / sum_j max(E1[v]E2[j], P1[v]P2[j])   (factorized leaky-softmax)

#define ALPHA 0.2f
#define LOG2E 1.4426950408889634f
constexpr int Bn = 8, Cn = 64, Tn = 256, Vn = 128, Fn = 64;

__device__ __forceinline__ unsigned smem_u32(const void* p) {
    unsigned a;
    asm("{ .reg .u64 t; cvta.to.shared.u64 t, %1; cvt.u32.u64 %0, t; }" : "=r"(a) : "l"(p));
    return a;
}
// pack two f32 -> bf16x2 (rn): result[15:0]=first arg, [31:16]=second arg
__device__ __forceinline__ unsigned pack_bf16(float lo_elem, float hi_elem) {
    unsigned r;
    asm("cvt.rn.bf16x2.f32 %0, %1, %2;" : "=r"(r) : "f"(hi_elem), "f"(lo_elem));
    return r;
}
__device__ __forceinline__ void ldsm4(unsigned* r, unsigned addr) {
    asm volatile("ldmatrix.sync.aligned.m8n8.x4.shared.b16 {%0,%1,%2,%3}, [%4];"
                 : "=r"(r[0]), "=r"(r[1]), "=r"(r[2]), "=r"(r[3]) : "r"(addr));
}
__device__ __forceinline__ void mma_bf16(float* c, const unsigned* a, const unsigned* b) {
    asm volatile(
        "mma.sync.aligned.m16n8k16.row.col.f32.bf16.bf16.f32 "
        "{%0,%1,%2,%3}, {%4,%5,%6,%7}, {%8,%9}, {%0,%1,%2,%3};"
        : "+f"(c[0]), "+f"(c[1]), "+f"(c[2]), "+f"(c[3])
        : "r"(a[0]), "r"(a[1]), "r"(a[2]), "r"(a[3]), "r"(b[0]), "r"(b[1]));
}
__device__ __forceinline__ unsigned bf16_bits(float f) {   // rn f32->bf16 bits
    unsigned u = __float_as_uint(f);
    return (u + 0x7FFFu + ((u >> 16) & 1u)) >> 16;
}
// branchless ELU: r>0 -> r ; small-neg -> cubic ; else exp2-based
__device__ __forceinline__ float elu_fast(float r) {
    float em  = exp2f(r * LOG2E) - 1.0f;
    float pl  = r * fmaf(r, fmaf(r, 0.16666667f, 0.5f), 1.0f);
    float neg = (r > -0.03125f) ? pl : em;
    return (r > 0.f) ? r : neg;
}

// ---- prep: W[c][f] f32 -> swizzled bf16 W^T images [f][c] (hi, lo) ----
__device__ unsigned char g_WThi[Fn * 128];
__device__ unsigned char g_WTlo[Fn * 128];

__global__ __launch_bounds__(256) void prep_kernel(const float* __restrict__ W) {
    for (int idx = threadIdx.x; idx < Fn * Cn; idx += 256) {
        int f = idx >> 6, c = idx & 63;
        float w = W[c * Fn + f];
        unsigned hb = bf16_bits(w);
        float lo = w - __uint_as_float(hb << 16);
        unsigned lb = bf16_bits(lo);
        unsigned off = f * 128 + ((2 * c) ^ ((f & 7) << 4));
        *(unsigned short*)(g_WThi + off) = (unsigned short)hb;
        *(unsigned short*)(g_WTlo + off) = (unsigned short)lb;
    }
}

// ---- smem layout (float offsets) ----
#define OFF_A1    0      // 64
#define OFF_A2    64     // 64
#define OFF_E1    128    // 128  exp(s1)
#define OFF_P1    256    // 128  exp(0.2 s1)
#define OFF_E2    384    // 128  exp(s2)
#define OFF_P2    512    // 128  exp(0.2 s2)
#define OFF_S1P   640    // [2][128]
#define OFF_S2P   896    // [2][128]
#define OFF_DENP  1152   // [2][128]
#define OFF_DIAG  1408   // 128
#define OFF_AHI   1536   // 16KB: A_hi [v=128][c=64] bf16 swizzled
#define OFF_ALO   5632   // 16KB
#define OFF_WTHI  9728   // 8KB
#define OFF_WTLO  11776  // 8KB
#define SMEM_FLOATS 13824   // 55,296 B -> 4 CTAs/SM

extern __shared__ float smem[];

__global__ __launch_bounds__(256, 4)
void GraphAttentionLayer4D_78082505441863_kernel(
    const float* __restrict__ x, const float* __restrict__ a,
    float* __restrict__ out)
{
    const int t    = blockIdx.x;
    const int b    = blockIdx.y;
    const int tid  = threadIdx.x;
    const int wid  = tid >> 5, lane = tid & 31;
    const int g    = lane >> 2, ti = lane & 3;   // mma quad layout
    const unsigned sbase = smem_u32(smem);

    // ---- stage WT tiles (pre-swizzled byte images, 16KB) ----
    {
        const uint4* sh = (const uint4*)g_WThi;
        const uint4* sl = (const uint4*)g_WTlo;
        uint4* dh = (uint4*)(smem + OFF_WTHI);
        uint4* dl = (uint4*)(smem + OFF_WTLO);
        #pragma unroll
        for (int i = tid; i < 512; i += 256) { dh[i] = sh[i]; dl[i] = sl[i]; }
    }
    if (tid < 128) {
        float av = a[tid];
        if (tid < 64) smem[OFF_A1 + tid] = av;
        else          smem[OFF_A2 + tid - 64] = av;
    }

    // ---- fused load+split: x[b,c,t,v] -> A_hi/A_lo [v][c] bf16 swizzled ----
    {
        const int v  = tid & 127;
        const int c0 = (tid >> 7) << 5;
        const float* xp = x + ((size_t)b * Cn + c0) * (size_t)(Tn * Vn)
                            + (size_t)t * Vn + v;
        char* Ahi = (char*)smem + OFF_AHI * 4 + v * 128;
        char* Alo = (char*)smem + OFF_ALO * 4 + v * 128;
        const unsigned sw = (v & 7) << 4;
        #pragma unroll
        for (int k = 0; k < 8; k++) {
            int c = c0 + 4 * k;
            float f0 = xp[(size_t)(4 * k + 0) * (Tn * Vn)];
            float f1 = xp[(size_t)(4 * k + 1) * (Tn * Vn)];
            float f2 = xp[(size_t)(4 * k + 2) * (Tn * Vn)];
            float f3 = xp[(size_t)(4 * k + 3) * (Tn * Vn)];
            unsigned h0 = pack_bf16(f0, f1);
            unsigned h1 = pack_bf16(f2, f3);
            float l0 = f0 - __uint_as_float(h0 << 16);
            float l1 = f1 - __uint_as_float(h0 & 0xFFFF0000u);
            float l2 = f2 - __uint_as_float(h1 << 16);
            float l3 = f3 - __uint_as_float(h1 & 0xFFFF0000u);
            unsigned q0 = pack_bf16(l0, l1);
            unsigned q1 = pack_bf16(l2, l3);
            unsigned off = (unsigned)(2 * c) ^ sw;   // 8B-aligned
            *(uint2*)(Ahi + off) = make_uint2(h0, h1);
            *(uint2*)(Alo + off) = make_uint2(q0, q1);
        }
    }
    __syncthreads();

    // ---- MMA mainloop: D[v=128][f=64], 3 split passes, low reg pressure ----
    const int wm = wid & 3, wn = wid >> 2;
    const int vbase = wm * 32, fbase = wn * 32;

    const unsigned q = lane >> 3, r = lane & 7;
    const unsigned rA  = vbase + (q & 1) * 8 + r;
    const unsigned cAq = (q >> 1) * 16;
    const unsigned swA = (rA & 7) << 4;
    const unsigned rB  = fbase + (q >> 1) * 8 + r;
    const unsigned cBq = (q & 1) * 16;
    const unsigned swB = (rB & 7) << 4;

    const unsigned pAhi = sbase + OFF_AHI  * 4 + rA * 128;
    const unsigned pAlo = sbase + OFF_ALO  * 4 + rA * 128;
    const unsigned pBhi = sbase + OFF_WTHI * 4 + rB * 128;
    const unsigned pBlo = sbase + OFF_WTLO * 4 + rB * 128;

    float acc[2][4][4];
    #pragma unroll
    for (int i = 0; i < 2; i++)
        #pragma unroll
        for (int j = 0; j < 4; j++)
            #pragma unroll
            for (int e = 0; e < 4; e++) acc[i][j][e] = 0.f;

    #pragma unroll
    for (int ks = 0; ks < 4; ks++) {
        const unsigned cA = (32 * ks + cAq) ^ swA;
        const unsigned cB = (32 * ks + cBq) ^ swB;
        unsigned ax[8], bx[4];
        ldsm4(ax,     pAhi + cA);
        ldsm4(ax + 4, pAhi + 2048 + cA);
        ldsm4(bx, pBhi + cB);
        mma_bf16(acc[0][0], ax, bx);     mma_bf16(acc[0][1], ax, bx + 2);
        mma_bf16(acc[1][0], ax + 4, bx); mma_bf16(acc[1][1], ax + 4, bx + 2);
        ldsm4(bx, pBhi + 2048 + cB);
        mma_bf16(acc[0][2], ax, bx);     mma_bf16(acc[0][3], ax, bx + 2);
        mma_bf16(acc[1][2], ax + 4, bx); mma_bf16(acc[1][3], ax + 4, bx + 2);
        ldsm4(bx, pBlo + cB);
        mma_bf16(acc[0][0], ax, bx);     mma_bf16(acc[0][1], ax, bx + 2);
        mma_bf16(acc[1][0], ax + 4, bx); mma_bf16(acc[1][1], ax + 4, bx + 2);
        ldsm4(bx, pBlo + 2048 + cB);
        mma_bf16(acc[0][2], ax, bx);     mma_bf16(acc[0][3], ax, bx + 2);
        mma_bf16(acc[1][2], ax + 4, bx); mma_bf16(acc[1][3], ax + 4, bx + 2);
        ldsm4(ax,     pAlo + cA);
        ldsm4(ax + 4, pAlo + 2048 + cA);
        ldsm4(bx, pBhi + cB);
        mma_bf16(acc[0][0], ax, bx);     mma_bf16(acc[0][1], ax, bx + 2);
        mma_bf16(acc[1][0], ax + 4, bx); mma_bf16(acc[1][1], ax + 4, bx + 2);
        ldsm4(bx, pBhi + 2048 + cB);
        mma_bf16(acc[0][2], ax, bx);     mma_bf16(acc[0][3], ax, bx + 2);
        mma_bf16(acc[1][2], ax + 4, bx); mma_bf16(acc[1][3], ax + 4, bx + 2);
    }

    // Accumulator element (i,j,e): v = vbase+16i+g+8*(e>>1), f = fbase+8j+2ti+(e&1)

    // ---- s1/s2 partials from accumulators + quad butterfly reduce ----
    {
        float s1r[4] = {0.f, 0.f, 0.f, 0.f};
        float s2r[4] = {0.f, 0.f, 0.f, 0.f};
        #pragma unroll
        for (int j = 0; j < 4; j++) {
            float w1a = smem[OFF_A1 + fbase + 8 * j + 2 * ti];
            float w1b = smem[OFF_A1 + fbase + 8 * j + 2 * ti + 1];
            float w2a = smem[OFF_A2 + fbase + 8 * j + 2 * ti];
            float w2b = smem[OFF_A2 + fbase + 8 * j + 2 * ti + 1];
            #pragma unroll
            for (int i = 0; i < 2; i++) {
                s1r[2 * i]     += acc[i][j][0] * w1a + acc[i][j][1] * w1b;
                s1r[2 * i + 1] += acc[i][j][2] * w1a + acc[i][j][3] * w1b;
                s2r[2 * i]     += acc[i][j][0] * w2a + acc[i][j][1] * w2b;
                s2r[2 * i + 1] += acc[i][j][2] * w2a + acc[i][j][3] * w2b;
            }
        }
        #pragma unroll
        for (int k = 0; k < 4; k++) {
            s1r[k] += __shfl_xor_sync(0xFFFFFFFFu, s1r[k], 1);
            s1r[k] += __shfl_xor_sync(0xFFFFFFFFu, s1r[k], 2);
            s2r[k] += __shfl_xor_sync(0xFFFFFFFFu, s2r[k], 1);
            s2r[k] += __shfl_xor_sync(0xFFFFFFFFu, s2r[k], 2);
        }
        if (ti == 0) {
            #pragma unroll
            for (int k = 0; k < 4; k++)
                smem[OFF_S1P + wn * 128 + vbase + 16 * (k >> 1) + 8 * (k & 1) + g] = s1r[k];
        } else if (ti == 1) {
            #pragma unroll
            for (int k = 0; k < 4; k++)
                smem[OFF_S2P + wn * 128 + vbase + 16 * (k >> 1) + 8 * (k & 1) + g] = s2r[k];
        }
    }
    __syncthreads();

    // ---- reduce + factorized exps: E = exp(s), P = exp(0.2 s) ----
    if (tid < 128) {
        float s1 = smem[OFF_S1P + tid] + smem[OFF_S1P + 128 + tid];
        smem[OFF_E1 + tid] = exp2f(s1 * LOG2E);
        smem[OFF_P1 + tid] = exp2f(s1 * (ALPHA * LOG2E));
    } else {
        int vv = tid - 128;
        float s2 = smem[OFF_S2P + vv] + smem[OFF_S2P + 128 + vv];
        smem[OFF_E2 + vv] = exp2f(s2 * LOG2E);
        smem[OFF_P2 + vv] = exp2f(s2 * (ALPHA * LOG2E));
    }
    __syncthreads();

    // ---- den[v] = sum_j max(E1[v]E2[j], P1[v]P2[j])  (pure FMA-pipe) ----
    {
        const int vv = tid & 127, half = tid >> 7;
        float E1v = smem[OFF_E1 + vv], P1v = smem[OFF_P1 + vv];
        float den = 0.f;
        const float4* E2q = (const float4*)(smem + OFF_E2) + half * 16;
        const float4* P2q = (const float4*)(smem + OFF_P2) + half * 16;
        #pragma unroll 8
        for (int j = 0; j < 16; j++) {
            float4 e2 = E2q[j];
            float4 p2 = P2q[j];
            den += fmaxf(E1v * e2.x, P1v * p2.x) + fmaxf(E1v * e2.y, P1v * p2.y)
                 + fmaxf(E1v * e2.z, P1v * p2.z) + fmaxf(E1v * e2.w, P1v * p2.w);
        }
        smem[OFF_DENP + half * 128 + vv] = den;
    }
    __syncthreads();
    if (tid < 128) {
        float den = smem[OFF_DENP + tid] + smem[OFF_DENP + 128 + tid];
        float num = fmaxf(smem[OFF_E1 + tid] * smem[OFF_E2 + tid],
                          smem[OFF_P1 + tid] * smem[OFF_P2 + tid]);
        smem[OFF_DIAG + tid] = num / den;
    }
    __syncthreads();

    // ---- out[b][f][t][v] = elu(diag[v] * acc) ; 32B-contiguous STG.32 ----
    {
        float dg[4];
        #pragma unroll
        for (int k = 0; k < 4; k++)
            dg[k] = smem[OFF_DIAG + vbase + 16 * (k >> 1) + 8 * (k & 1) + g];
        #pragma unroll
        for (int i = 0; i < 2; i++) {
            const int v0 = vbase + 16 * i + g;
            #pragma unroll
            for (int j = 0; j < 4; j++) {
                const int f = fbase + 8 * j + 2 * ti;
                float* ob = out + ((size_t)(b * Fn + f) * Tn + t) * Vn;
                ob[v0]               = elu_fast(dg[2 * i]     * acc[i][j][0]);
                ob[Tn * Vn + v0]     = elu_fast(dg[2 * i]     * acc[i][j][1]);
                ob[v0 + 8]           = elu_fast(dg[2 * i + 1] * acc[i][j][2]);
                ob[Tn * Vn + v0 + 8] = elu_fast(dg[2 * i + 1] * acc[i][j][3]);
            }
        }
    }
}

extern "C" void kernel_launch(void* const* d_in, const int* in_sizes, int n_in,
                              void* d_out, int out_size)
{
    const float* x = (const float*)d_in[0];
    const float* W = (const float*)d_in[1];
    const float* a = (const float*)d_in[2];
    float* out = (float*)d_out;

    cudaFuncSetAttribute(GraphAttentionLayer4D_78082505441863_kernel,
                         cudaFuncAttributeMaxDynamicSharedMemorySize,
                         SMEM_FLOATS * (int)sizeof(float));

    prep_kernel<<<1, 256>>>(W);

    dim3 grid(Tn, Bn);   // one CTA per (t, b): 2048 CTAs
    GraphAttentionLayer4D_78082505441863_kernel
        <<<grid, 256, SMEM_FLOATS * sizeof(float)>>>(x, a, out);
}

// round 9
// speedup vs baseline: 1.0260x; 1.0260x over previous
#include <cuda_runtime.h>

// out[b][f][t][v] = elu(diag[b,v,t] * Wh[b,v,t,f])
//   Wh[b,v,t,f] = sum_c x[b,c,t,v] * W[c,f]      <-- mma.sync bf16 3-pass split
//   s1[v] = Wh[v,:]·a1 ; s2[v] = Wh[v,:]·a2       (per b,t)
//   diag[v] = num(v) / sum_j max(E1[v]E2[j], P1[v]P2[j])   (factorized leaky-softmax)

#define ALPHA 0.2f
#define LOG2E 1.4426950408889634f
constexpr int Bn = 8, Cn = 64, Tn = 256, Vn = 128, Fn = 64;

__device__ __forceinline__ unsigned smem_u32(const void* p) {
    unsigned a;
    asm("{ .reg .u64 t; cvta.to.shared.u64 t, %1; cvt.u32.u64 %0, t; }" : "=r"(a) : "l"(p));
    return a;
}
// pack two f32 -> bf16x2 (rn): result[15:0]=first arg, [31:16]=second arg
__device__ __forceinline__ unsigned pack_bf16(float lo_elem, float hi_elem) {
    unsigned r;
    asm("cvt.rn.bf16x2.f32 %0, %1, %2;" : "=r"(r) : "f"(hi_elem), "f"(lo_elem));
    return r;
}
__device__ __forceinline__ void ldsm4(unsigned* r, unsigned addr) {
    asm volatile("ldmatrix.sync.aligned.m8n8.x4.shared.b16 {%0,%1,%2,%3}, [%4];"
                 : "=r"(r[0]), "=r"(r[1]), "=r"(r[2]), "=r"(r[3]) : "r"(addr));
}
__device__ __forceinline__ void mma_bf16(float* c, const unsigned* a, const unsigned* b) {
    asm volatile(
        "mma.sync.aligned.m16n8k16.row.col.f32.bf16.bf16.f32 "
        "{%0,%1,%2,%3}, {%4,%5,%6,%7}, {%8,%9}, {%0,%1,%2,%3};"
        : "+f"(c[0]), "+f"(c[1]), "+f"(c[2]), "+f"(c[3])
        : "r"(a[0]), "r"(a[1]), "r"(a[2]), "r"(a[3]), "r"(b[0]), "r"(b[1]));
}
__device__ __forceinline__ unsigned bf16_bits(float f) {   // rn f32->bf16 bits
    unsigned u = __float_as_uint(f);
    return (u + 0x7FFFu + ((u >> 16) & 1u)) >> 16;
}
// branchless ELU: r>0 -> r ; small-neg -> cubic ; else exp2-based
__device__ __forceinline__ float elu_fast(float r) {
    float em  = exp2f(r * LOG2E) - 1.0f;
    float pl  = r * fmaf(r, fmaf(r, 0.16666667f, 0.5f), 1.0f);
    float neg = (r > -0.03125f) ? pl : em;
    return (r > 0.f) ? r : neg;
}

// ---- prep: W[c][f] f32 -> swizzled bf16 W^T images [f][c] (hi, lo) ----
__device__ unsigned char g_WThi[Fn * 128];
__device__ unsigned char g_WTlo[Fn * 128];

__global__ __launch_bounds__(256) void prep_kernel(const float* __restrict__ W) {
    for (int idx = threadIdx.x; idx < Fn * Cn; idx += 256) {
        int f = idx >> 6, c = idx & 63;
        float w = W[c * Fn + f];
        unsigned hb = bf16_bits(w);
        float lo = w - __uint_as_float(hb << 16);
        unsigned lb = bf16_bits(lo);
        unsigned off = f * 128 + ((2 * c) ^ ((f & 7) << 4));
        *(unsigned short*)(g_WThi + off) = (unsigned short)hb;
        *(unsigned short*)(g_WTlo + off) = (unsigned short)lb;
    }
}

// ---- smem layout (float offsets) ----
#define OFF_A1    0      // 64
#define OFF_A2    64     // 64
#define OFF_E1    128    // 128  exp(s1)
#define OFF_P1    256    // 128  exp(0.2 s1)
#define OFF_E2    384    // 128  exp(s2)
#define OFF_P2    512    // 128  exp(0.2 s2)
#define OFF_S1P   640    // [2][128]
#define OFF_S2P   896    // [2][128]
#define OFF_DENP  1152   // [2][128]
#define OFF_DIAG  1408   // 128
#define OFF_AHI   1536   // 16KB: A_hi [v=128][c=64] bf16 swizzled
#define OFF_ALO   5632   // 16KB
#define OFF_WTHI  9728   // 8KB
#define OFF_WTLO  11776  // 8KB
#define SMEM_FLOATS 13824   // 55,296 B -> 4 CTAs/SM

extern __shared__ float smem[];

__global__ __launch_bounds__(256, 4)
void GraphAttentionLayer4D_78082505441863_kernel(
    const float* __restrict__ x, const float* __restrict__ a,
    float* __restrict__ out)
{
    const int t    = blockIdx.x;
    const int b    = blockIdx.y;
    const int tid  = threadIdx.x;
    const int wid  = tid >> 5, lane = tid & 31;
    const int g    = lane >> 2, ti = lane & 3;   // mma quad layout
    const unsigned sbase = smem_u32(smem);

    // ---- stage WT tiles (pre-swizzled byte images, 16KB; L1-resident) ----
    {
        const uint4* sh = (const uint4*)g_WThi;
        const uint4* sl = (const uint4*)g_WTlo;
        uint4* dh = (uint4*)(smem + OFF_WTHI);
        uint4* dl = (uint4*)(smem + OFF_WTLO);
        #pragma unroll
        for (int i = tid; i < 512; i += 256) { dh[i] = sh[i]; dl[i] = sl[i]; }
    }
    if (tid < 128) {
        float av = a[tid];
        if (tid < 64) smem[OFF_A1 + tid] = av;
        else          smem[OFF_A2 + tid - 64] = av;
    }

    // ---- fused load+split: x[b,c,t,v] -> A_hi/A_lo [v][c] bf16 swizzled ----
    // (1) batch ALL 32 LDGs first: MLP=32, single latency exposure
    // (2) STS.128 16B chunks: swizzled columns tile all 32 banks -> conflict-free
    {
        const int v  = tid & 127;
        const int c0 = (tid >> 7) << 5;
        const float* xp = x + ((size_t)b * Cn + c0) * (size_t)(Tn * Vn)
                            + (size_t)t * Vn + v;
        float xr[32];
        #pragma unroll
        for (int k = 0; k < 32; k++)
            xr[k] = xp[(size_t)k * (Tn * Vn)];

        char* Ahi = (char*)smem + OFF_AHI * 4 + v * 128;
        char* Alo = (char*)smem + OFF_ALO * 4 + v * 128;
        const unsigned sw = (v & 7) << 4;
        #pragma unroll
        for (int m = 0; m < 4; m++) {          // 16B chunk: c in [c0+8m, c0+8m+8)
            const float* xc = xr + 8 * m;
            unsigned h0 = pack_bf16(xc[0], xc[1]);
            unsigned h1 = pack_bf16(xc[2], xc[3]);
            unsigned h2 = pack_bf16(xc[4], xc[5]);
            unsigned h3 = pack_bf16(xc[6], xc[7]);
            float l0 = xc[0] - __uint_as_float(h0 << 16);
            float l1 = xc[1] - __uint_as_float(h0 & 0xFFFF0000u);
            float l2 = xc[2] - __uint_as_float(h1 << 16);
            float l3 = xc[3] - __uint_as_float(h1 & 0xFFFF0000u);
            float l4 = xc[4] - __uint_as_float(h2 << 16);
            float l5 = xc[5] - __uint_as_float(h2 & 0xFFFF0000u);
            float l6 = xc[6] - __uint_as_float(h3 << 16);
            float l7 = xc[7] - __uint_as_float(h3 & 0xFFFF0000u);
            unsigned q0 = pack_bf16(l0, l1);
            unsigned q1 = pack_bf16(l2, l3);
            unsigned q2 = pack_bf16(l4, l5);
            unsigned q3 = pack_bf16(l6, l7);
            unsigned off = (unsigned)(2 * (c0 + 8 * m)) ^ sw;   // 16B-aligned
            *(uint4*)(Ahi + off) = make_uint4(h0, h1, h2, h3);
            *(uint4*)(Alo + off) = make_uint4(q0, q1, q2, q3);
        }
    }
    __syncthreads();

    // ---- MMA mainloop: D[v=128][f=64], 3 split passes, low reg pressure ----
    const int wm = wid & 3, wn = wid >> 2;
    const int vbase = wm * 32, fbase = wn * 32;

    const unsigned q = lane >> 3, r = lane & 7;
    const unsigned rA  = vbase + (q & 1) * 8 + r;
    const unsigned cAq = (q >> 1) * 16;
    const unsigned swA = (rA & 7) << 4;
    const unsigned rB  = fbase + (q >> 1) * 8 + r;
    const unsigned cBq = (q & 1) * 16;
    const unsigned swB = (rB & 7) << 4;

    const unsigned pAhi = sbase + OFF_AHI  * 4 + rA * 128;
    const unsigned pAlo = sbase + OFF_ALO  * 4 + rA * 128;
    const unsigned pBhi = sbase + OFF_WTHI * 4 + rB * 128;
    const unsigned pBlo = sbase + OFF_WTLO * 4 + rB * 128;

    float acc[2][4][4];
    #pragma unroll
    for (int i = 0; i < 2; i++)
        #pragma unroll
        for (int j = 0; j < 4; j++)
            #pragma unroll
            for (int e = 0; e < 4; e++) acc[i][j][e] = 0.f;

    #pragma unroll
    for (int ks = 0; ks < 4; ks++) {
        const unsigned cA = (32 * ks + cAq) ^ swA;
        const unsigned cB = (32 * ks + cBq) ^ swB;
        unsigned ax[8], bx[4];
        ldsm4(ax,     pAhi + cA);
        ldsm4(ax + 4, pAhi + 2048 + cA);
        ldsm4(bx, pBhi + cB);
        mma_bf16(acc[0][0], ax, bx);     mma_bf16(acc[0][1], ax, bx + 2);
        mma_bf16(acc[1][0], ax + 4, bx); mma_bf16(acc[1][1], ax + 4, bx + 2);
        ldsm4(bx, pBhi + 2048 + cB);
        mma_bf16(acc[0][2], ax, bx);     mma_bf16(acc[0][3], ax, bx + 2);
        mma_bf16(acc[1][2], ax + 4, bx); mma_bf16(acc[1][3], ax + 4, bx + 2);
        ldsm4(bx, pBlo + cB);
        mma_bf16(acc[0][0], ax, bx);     mma_bf16(acc[0][1], ax, bx + 2);
        mma_bf16(acc[1][0], ax + 4, bx); mma_bf16(acc[1][1], ax + 4, bx + 2);
        ldsm4(bx, pBlo + 2048 + cB);
        mma_bf16(acc[0][2], ax, bx);     mma_bf16(acc[0][3], ax, bx + 2);
        mma_bf16(acc[1][2], ax + 4, bx); mma_bf16(acc[1][3], ax + 4, bx + 2);
        ldsm4(ax,     pAlo + cA);
        ldsm4(ax + 4, pAlo + 2048 + cA);
        ldsm4(bx, pBhi + cB);
        mma_bf16(acc[0][0], ax, bx);     mma_bf16(acc[0][1], ax, bx + 2);
        mma_bf16(acc[1][0], ax + 4, bx); mma_bf16(acc[1][1], ax + 4, bx + 2);
        ldsm4(bx, pBhi + 2048 + cB);
        mma_bf16(acc[0][2], ax, bx);     mma_bf16(acc[0][3], ax, bx + 2);
        mma_bf16(acc[1][2], ax + 4, bx); mma_bf16(acc[1][3], ax + 4, bx + 2);
    }

    // Accumulator element (i,j,e): v = vbase+16i+g+8*(e>>1), f = fbase+8j+2ti+(e&1)

    // ---- s1/s2 partials from accumulators + quad butterfly reduce ----
    {
        float s1r[4] = {0.f, 0.f, 0.f, 0.f};
        float s2r[4] = {0.f, 0.f, 0.f, 0.f};
        #pragma unroll
        for (int j = 0; j < 4; j++) {
            float w1a = smem[OFF_A1 + fbase + 8 * j + 2 * ti];
            float w1b = smem[OFF_A1 + fbase + 8 * j + 2 * ti + 1];
            float w2a = smem[OFF_A2 + fbase + 8 * j + 2 * ti];
            float w2b = smem[OFF_A2 + fbase + 8 * j + 2 * ti + 1];
            #pragma unroll
            for (int i = 0; i < 2; i++) {
                s1r[2 * i]     += acc[i][j][0] * w1a + acc[i][j][1] * w1b;
                s1r[2 * i + 1] += acc[i][j][2] * w1a + acc[i][j][3] * w1b;
                s2r[2 * i]     += acc[i][j][0] * w2a + acc[i][j][1] * w2b;
                s2r[2 * i + 1] += acc[i][j][2] * w2a + acc[i][j][3] * w2b;
            }
        }
        #pragma unroll
        for (int k = 0; k < 4; k++) {
            s1r[k] += __shfl_xor_sync(0xFFFFFFFFu, s1r[k], 1);
            s1r[k] += __shfl_xor_sync(0xFFFFFFFFu, s1r[k], 2);
            s2r[k] += __shfl_xor_sync(0xFFFFFFFFu, s2r[k], 1);
            s2r[k] += __shfl_xor_sync(0xFFFFFFFFu, s2r[k], 2);
        }
        if (ti == 0) {
            #pragma unroll
            for (int k = 0; k < 4; k++)
                smem[OFF_S1P + wn * 128 + vbase + 16 * (k >> 1) + 8 * (k & 1) + g] = s1r[k];
        } else if (ti == 1) {
            #pragma unroll
            for (int k = 0; k < 4; k++)
                smem[OFF_S2P + wn * 128 + vbase + 16 * (k >> 1) + 8 * (k & 1) + g] = s2r[k];
        }
    }
    __syncthreads();

    // ---- reduce + factorized exps: E = exp(s), P = exp(0.2 s) ----
    if (tid < 128) {
        float s1 = smem[OFF_S1P + tid] + smem[OFF_S1P + 128 + tid];
        smem[OFF_E1 + tid] = exp2f(s1 * LOG2E);
        smem[OFF_P1 + tid] = exp2f(s1 * (ALPHA * LOG2E));
    } else {
        int vv = tid - 128;
        float s2 = smem[OFF_S2P + vv] + smem[OFF_S2P + 128 + vv];
        smem[OFF_E2 + vv] = exp2f(s2 * LOG2E);
        smem[OFF_P2 + vv] = exp2f(s2 * (ALPHA * LOG2E));
    }
    __syncthreads();

    // ---- den[v] = sum_j max(E1[v]E2[j], P1[v]P2[j])  (pure FMA-pipe) ----
    {
        const int vv = tid & 127, half = tid >> 7;
        float E1v = smem[OFF_E1 + vv], P1v = smem[OFF_P1 + vv];
        float den = 0.f;
        const float4* E2q = (const float4*)(smem + OFF_E2) + half * 16;
        const float4* P2q = (const float4*)(smem + OFF_P2) + half * 16;
        #pragma unroll 8
        for (int j = 0; j < 16; j++) {
            float4 e2 = E2q[j];
            float4 p2 = P2q[j];
            den += fmaxf(E1v * e2.x, P1v * p2.x) + fmaxf(E1v * e2.y, P1v * p2.y)
                 + fmaxf(E1v * e2.z, P1v * p2.z) + fmaxf(E1v * e2.w, P1v * p2.w);
        }
        smem[OFF_DENP + half * 128 + vv] = den;
    }
    __syncthreads();
    if (tid < 128) {
        float den = smem[OFF_DENP + tid] + smem[OFF_DENP + 128 + tid];
        float num = fmaxf(smem[OFF_E1 + tid] * smem[OFF_E2 + tid],
                          smem[OFF_P1 + tid] * smem[OFF_P2 + tid]);
        smem[OFF_DIAG + tid] = num / den;
    }
    __syncthreads();

    // ---- out[b][f][t][v] = elu(diag[v] * acc) ; 32B-contiguous STG.32 ----
    {
        float dg[4];
        #pragma unroll
        for (int k = 0; k < 4; k++)
            dg[k] = smem[OFF_DIAG + vbase + 16 * (k >> 1) + 8 * (k & 1) + g];
        #pragma unroll
        for (int i = 0; i < 2; i++) {
            const int v0 = vbase + 16 * i + g;
            #pragma unroll
            for (int j = 0; j < 4; j++) {
                const int f = fbase + 8 * j + 2 * ti;
                float* ob = out + ((size_t)(b * Fn + f) * Tn + t) * Vn;
                ob[v0]               = elu_fast(dg[2 * i]     * acc[i][j][0]);
                ob[Tn * Vn + v0]     = elu_fast(dg[2 * i]     * acc[i][j][1]);
                ob[v0 + 8]           = elu_fast(dg[2 * i + 1] * acc[i][j][2]);
                ob[Tn * Vn + v0 + 8] = elu_fast(dg[2 * i + 1] * acc[i][j][3]);
            }
        }
    }
}

extern "C" void kernel_launch(void* const* d_in, const int* in_sizes, int n_in,
                              void* d_out, int out_size)
{
    const float* x = (const float*)d_in[0];
    const float* W = (const float*)d_in[1];
    const float* a = (const float*)d_in[2];
    float* out = (float*)d_out;

    cudaFuncSetAttribute(GraphAttentionLayer4D_78082505441863_kernel,
                         cudaFuncAttributeMaxDynamicSharedMemorySize,
                         SMEM_FLOATS * (int)sizeof(float));

    prep_kernel<<<1, 256>>>(W);

    dim3 grid(Tn, Bn);   // one CTA per (t, b): 2048 CTAs
    GraphAttentionLayer4D_78082505441863_kernel
        <<<grid, 256, SMEM_FLOATS * sizeof(float)>>>(x, a, out);
}

// round 10
// speedup vs baseline: 1.1279x; 1.0992x over previous
#include <cuda_runtime.h>

// out[b][f][t][v] = elu(diag[b,v,t] * Wh[b,v,t,f])
//   Wh[b,v,t,f] = sum_c x[b,c,t,v] * W[c,f]      <-- mma.sync bf16 3-pass split
//   s1[v] = Wh[v,:]·a1 ; s2[v] = Wh[v,:]·a2       (per b,t)
//   diag[v] = num(v) / sum_j max(E1[v]E2[j], P1[v]P2[j])   (factorized leaky-softmax)

#define ALPHA 0.2f
#define LOG2E 1.4426950408889634f
constexpr int Bn = 8, Cn = 64, Tn = 256, Vn = 128, Fn = 64;

__device__ __forceinline__ unsigned smem_u32(const void* p) {
    unsigned a;
    asm("{ .reg .u64 t; cvta.to.shared.u64 t, %1; cvt.u32.u64 %0, t; }" : "=r"(a) : "l"(p));
    return a;
}
// pack two f32 -> bf16x2 (rn): result[15:0]=first arg, [31:16]=second arg
__device__ __forceinline__ unsigned pack_bf16(float lo_elem, float hi_elem) {
    unsigned r;
    asm("cvt.rn.bf16x2.f32 %0, %1, %2;" : "=r"(r) : "f"(hi_elem), "f"(lo_elem));
    return r;
}
__device__ __forceinline__ void ldsm4(unsigned* r, unsigned addr) {
    asm volatile("ldmatrix.sync.aligned.m8n8.x4.shared.b16 {%0,%1,%2,%3}, [%4];"
                 : "=r"(r[0]), "=r"(r[1]), "=r"(r[2]), "=r"(r[3]) : "r"(addr));
}
__device__ __forceinline__ void mma_bf16(float* c, const unsigned* a, const unsigned* b) {
    asm volatile(
        "mma.sync.aligned.m16n8k16.row.col.f32.bf16.bf16.f32 "
        "{%0,%1,%2,%3}, {%4,%5,%6,%7}, {%8,%9}, {%0,%1,%2,%3};"
        : "+f"(c[0]), "+f"(c[1]), "+f"(c[2]), "+f"(c[3])
        : "r"(a[0]), "r"(a[1]), "r"(a[2]), "r"(a[3]), "r"(b[0]), "r"(b[1]));
}
__device__ __forceinline__ unsigned bf16_bits(float f) {   // rn f32->bf16 bits
    unsigned u = __float_as_uint(f);
    return (u + 0x7FFFu + ((u >> 16) & 1u)) >> 16;
}
// branchless ELU: r>0 -> r ; small-neg -> cubic ; else exp2-based
__device__ __forceinline__ float elu_fast(float r) {
    float em  = exp2f(r * LOG2E) - 1.0f;
    float pl  = r * fmaf(r, fmaf(r, 0.16666667f, 0.5f), 1.0f);
    float neg = (r > -0.03125f) ? pl : em;
    return (r > 0.f) ? r : neg;
}

// ---- B-fragment table: [wn(2)][ks(4)][ph(4: hi-h0, hi-h1, lo-h0, lo-h1)][lane(32)] ----
// Each entry is the exact uint4 an ldsm4 would deliver to that lane. 16KB, L2-hot.
__device__ uint4 g_Btab[2 * 4 * 4 * 32];

__global__ __launch_bounds__(256) void prep_kernel(const float* __restrict__ W) {
    __shared__ unsigned char ps[16384];   // WT hi [0,8K), WT lo [8K,16K)
    const int tid = threadIdx.x;

    // build swizzled WT images (same layout main kernel used to stage)
    for (int idx = tid; idx < Fn * Cn; idx += 256) {
        int f = idx >> 6, c = idx & 63;
        float w = W[c * Fn + f];
        unsigned hb = bf16_bits(w);
        float lo = w - __uint_as_float(hb << 16);
        unsigned lb = bf16_bits(lo);
        unsigned off = f * 128 + ((2 * c) ^ ((f & 7) << 4));
        *(unsigned short*)(ps + off)        = (unsigned short)hb;
        *(unsigned short*)(ps + 8192 + off) = (unsigned short)lb;
    }
    __syncthreads();

    // warp 0 replays the main kernel's ldmatrix addressing and dumps fragments
    if (tid < 32) {
        const unsigned lane = tid, q = lane >> 3, r = lane & 7;
        const unsigned sb = smem_u32(ps);
        for (int wn = 0; wn < 2; wn++) {
            const unsigned rB  = wn * 32 + (q >> 1) * 8 + r;
            const unsigned swB = (rB & 7) << 4;
            const unsigned rowb = rB * 128;
            for (int ks = 0; ks < 4; ks++) {
                const unsigned cB = (32 * ks + (q & 1) * 16) ^ swB;
                unsigned bx[4];
                const int base = ((wn * 4 + ks) * 4) * 32 + lane;
                ldsm4(bx, sb + rowb + cB);                    // hi, n-half 0
                g_Btab[base]      = make_uint4(bx[0], bx[1], bx[2], bx[3]);
                ldsm4(bx, sb + 2048 + rowb + cB);             // hi, n-half 1
                g_Btab[base + 32] = make_uint4(bx[0], bx[1], bx[2], bx[3]);
                ldsm4(bx, sb + 8192 + rowb + cB);             // lo, n-half 0
                g_Btab[base + 64] = make_uint4(bx[0], bx[1], bx[2], bx[3]);
                ldsm4(bx, sb + 8192 + 2048 + rowb + cB);      // lo, n-half 1
                g_Btab[base + 96] = make_uint4(bx[0], bx[1], bx[2], bx[3]);
            }
        }
    }
}

// ---- smem layout (float offsets) ----
#define OFF_A1    0      // 64
#define OFF_A2    64     // 64
#define OFF_E1    128    // 128  exp(s1)
#define OFF_P1    256    // 128  exp(0.2 s1)
#define OFF_E2    384    // 128  exp(s2)
#define OFF_P2    512    // 128  exp(0.2 s2)
#define OFF_S1P   640    // [2][128]
#define OFF_S2P   896    // [2][128]
#define OFF_DENP  1152   // [2][128]
#define OFF_DIAG  1408   // 128
#define OFF_AHI   1536   // 16KB: A_hi [v=128][c=64] bf16 swizzled
#define OFF_ALO   5632   // 16KB
#define SMEM_FLOATS 9728    // 38,912 B -> 4 CTAs/SM (reg-capped anyway)

extern __shared__ float smem[];

__global__ __launch_bounds__(256, 4)
void GraphAttentionLayer4D_78082505441863_kernel(
    const float* __restrict__ x, const float* __restrict__ a,
    float* __restrict__ out)
{
    const int t    = blockIdx.x;
    const int b    = blockIdx.y;
    const int tid  = threadIdx.x;
    const int wid  = tid >> 5, lane = tid & 31;
    const int g    = lane >> 2, ti = lane & 3;   // mma quad layout
    const unsigned sbase = smem_u32(smem);

    if (tid < 128) {
        float av = a[tid];
        if (tid < 64) smem[OFF_A1 + tid] = av;
        else          smem[OFF_A2 + tid - 64] = av;
    }

    // ---- fused load+split: x[b,c,t,v] -> A_hi/A_lo [v][c] bf16 swizzled ----
    // batch all 32 LDGs (MLP=32), then STS.128 conflict-free chunks
    {
        const int v  = tid & 127;
        const int c0 = (tid >> 7) << 5;
        const float* xp = x + ((size_t)b * Cn + c0) * (size_t)(Tn * Vn)
                            + (size_t)t * Vn + v;
        float xr[32];
        #pragma unroll
        for (int k = 0; k < 32; k++)
            xr[k] = xp[(size_t)k * (Tn * Vn)];

        char* Ahi = (char*)smem + OFF_AHI * 4 + v * 128;
        char* Alo = (char*)smem + OFF_ALO * 4 + v * 128;
        const unsigned sw = (v & 7) << 4;
        #pragma unroll
        for (int m = 0; m < 4; m++) {
            const float* xc = xr + 8 * m;
            unsigned h0 = pack_bf16(xc[0], xc[1]);
            unsigned h1 = pack_bf16(xc[2], xc[3]);
            unsigned h2 = pack_bf16(xc[4], xc[5]);
            unsigned h3 = pack_bf16(xc[6], xc[7]);
            float l0 = xc[0] - __uint_as_float(h0 << 16);
            float l1 = xc[1] - __uint_as_float(h0 & 0xFFFF0000u);
            float l2 = xc[2] - __uint_as_float(h1 << 16);
            float l3 = xc[3] - __uint_as_float(h1 & 0xFFFF0000u);
            float l4 = xc[4] - __uint_as_float(h2 << 16);
            float l5 = xc[5] - __uint_as_float(h2 & 0xFFFF0000u);
            float l6 = xc[6] - __uint_as_float(h3 << 16);
            float l7 = xc[7] - __uint_as_float(h3 & 0xFFFF0000u);
            unsigned q0 = pack_bf16(l0, l1);
            unsigned q1 = pack_bf16(l2, l3);
            unsigned q2 = pack_bf16(l4, l5);
            unsigned q3 = pack_bf16(l6, l7);
            unsigned off = (unsigned)(2 * (c0 + 8 * m)) ^ sw;   // 16B-aligned
            *(uint4*)(Ahi + off) = make_uint4(h0, h1, h2, h3);
            *(uint4*)(Alo + off) = make_uint4(q0, q1, q2, q3);
        }
    }
    __syncthreads();

    // ---- MMA mainloop: A via ldsm (each tile read once), B via LDG frag table ----
    const int wm = wid & 3, wn = wid >> 2;
    const int vbase = wm * 32, fbase = wn * 32;

    const unsigned q = lane >> 3, r = lane & 7;
    const unsigned rA  = vbase + (q & 1) * 8 + r;
    const unsigned cAq = (q >> 1) * 16;
    const unsigned swA = (rA & 7) << 4;

    const unsigned pAhi = sbase + OFF_AHI * 4 + rA * 128;
    const unsigned pAlo = sbase + OFF_ALO * 4 + rA * 128;
    const uint4* __restrict__ btb = g_Btab + wn * 512 + lane;

    float acc[2][4][4];
    #pragma unroll
    for (int i = 0; i < 2; i++)
        #pragma unroll
        for (int j = 0; j < 4; j++)
            #pragma unroll
            for (int e = 0; e < 4; e++) acc[i][j][e] = 0.f;

    #pragma unroll
    for (int ks = 0; ks < 4; ks++) {
        const unsigned cA = (32 * ks + cAq) ^ swA;
        unsigned ax[8], al[8];
        ldsm4(ax,     pAhi + cA);
        ldsm4(ax + 4, pAhi + 2048 + cA);
        ldsm4(al,     pAlo + cA);
        ldsm4(al + 4, pAlo + 2048 + cA);

        uint4 bq;
        bq = __ldg(btb + ks * 128);          // B-hi, n-half 0
        mma_bf16(acc[0][0], ax,     &bq.x); mma_bf16(acc[0][1], ax,     &bq.z);
        mma_bf16(acc[1][0], ax + 4, &bq.x); mma_bf16(acc[1][1], ax + 4, &bq.z);
        mma_bf16(acc[0][0], al,     &bq.x); mma_bf16(acc[0][1], al,     &bq.z);
        mma_bf16(acc[1][0], al + 4, &bq.x); mma_bf16(acc[1][1], al + 4, &bq.z);
        bq = __ldg(btb + ks * 128 + 32);     // B-hi, n-half 1
        mma_bf16(acc[0][2], ax,     &bq.x); mma_bf16(acc[0][3], ax,     &bq.z);
        mma_bf16(acc[1][2], ax + 4, &bq.x); mma_bf16(acc[1][3], ax + 4, &bq.z);
        mma_bf16(acc[0][2], al,     &bq.x); mma_bf16(acc[0][3], al,     &bq.z);
        mma_bf16(acc[1][2], al + 4, &bq.x); mma_bf16(acc[1][3], al + 4, &bq.z);
        bq = __ldg(btb + ks * 128 + 64);     // B-lo, n-half 0 (pairs with A-hi only)
        mma_bf16(acc[0][0], ax,     &bq.x); mma_bf16(acc[0][1], ax,     &bq.z);
        mma_bf16(acc[1][0], ax + 4, &bq.x); mma_bf16(acc[1][1], ax + 4, &bq.z);
        bq = __ldg(btb + ks * 128 + 96);     // B-lo, n-half 1
        mma_bf16(acc[0][2], ax,     &bq.x); mma_bf16(acc[0][3], ax,     &bq.z);
        mma_bf16(acc[1][2], ax + 4, &bq.x); mma_bf16(acc[1][3], ax + 4, &bq.z);
    }

    // Accumulator element (i,j,e): v = vbase+16i+g+8*(e>>1), f = fbase+8j+2ti+(e&1)

    // ---- s1/s2 partials from accumulators + quad butterfly reduce ----
    {
        float s1r[4] = {0.f, 0.f, 0.f, 0.f};
        float s2r[4] = {0.f, 0.f, 0.f, 0.f};
        #pragma unroll
        for (int j = 0; j < 4; j++) {
            float w1a = smem[OFF_A1 + fbase + 8 * j + 2 * ti];
            float w1b = smem[OFF_A1 + fbase + 8 * j + 2 * ti + 1];
            float w2a = smem[OFF_A2 + fbase + 8 * j + 2 * ti];
            float w2b = smem[OFF_A2 + fbase + 8 * j + 2 * ti + 1];
            #pragma unroll
            for (int i = 0; i < 2; i++) {
                s1r[2 * i]     += acc[i][j][0] * w1a + acc[i][j][1] * w1b;
                s1r[2 * i + 1] += acc[i][j][2] * w1a + acc[i][j][3] * w1b;
                s2r[2 * i]     += acc[i][j][0] * w2a + acc[i][j][1] * w2b;
                s2r[2 * i + 1] += acc[i][j][2] * w2a + acc[i][j][3] * w2b;
            }
        }
        #pragma unroll
        for (int k = 0; k < 4; k++) {
            s1r[k] += __shfl_xor_sync(0xFFFFFFFFu, s1r[k], 1);
            s1r[k] += __shfl_xor_sync(0xFFFFFFFFu, s1r[k], 2);
            s2r[k] += __shfl_xor_sync(0xFFFFFFFFu, s2r[k], 1);
            s2r[k] += __shfl_xor_sync(0xFFFFFFFFu, s2r[k], 2);
        }
        if (ti == 0) {
            #pragma unroll
            for (int k = 0; k < 4; k++)
                smem[OFF_S1P + wn * 128 + vbase + 16 * (k >> 1) + 8 * (k & 1) + g] = s1r[k];
        } else if (ti == 1) {
            #pragma unroll
            for (int k = 0; k < 4; k++)
                smem[OFF_S2P + wn * 128 + vbase + 16 * (k >> 1) + 8 * (k & 1) + g] = s2r[k];
        }
    }
    __syncthreads();

    // ---- reduce + factorized exps: E = exp(s), P = exp(0.2 s) ----
    if (tid < 128) {
        float s1 = smem[OFF_S1P + tid] + smem[OFF_S1P + 128 + tid];
        smem[OFF_E1 + tid] = exp2f(s1 * LOG2E);
        smem[OFF_P1 + tid] = exp2f(s1 * (ALPHA * LOG2E));
    } else {
        int vv = tid - 128;
        float s2 = smem[OFF_S2P + vv] + smem[OFF_S2P + 128 + vv];
        smem[OFF_E2 + vv] = exp2f(s2 * LOG2E);
        smem[OFF_P2 + vv] = exp2f(s2 * (ALPHA * LOG2E));
    }
    __syncthreads();

    // ---- den[v] = sum_j max(E1[v]E2[j], P1[v]P2[j])  (pure FMA-pipe) ----
    {
        const int vv = tid & 127, half = tid >> 7;
        float E1v = smem[OFF_E1 + vv], P1v = smem[OFF_P1 + vv];
        float den = 0.f;
        const float4* E2q = (const float4*)(smem + OFF_E2) + half * 16;
        const float4* P2q = (const float4*)(smem + OFF_P2) + half * 16;
        #pragma unroll 8
        for (int j = 0; j < 16; j++) {
            float4 e2 = E2q[j];
            float4 p2 = P2q[j];
            den += fmaxf(E1v * e2.x, P1v * p2.x) + fmaxf(E1v * e2.y, P1v * p2.y)
                 + fmaxf(E1v * e2.z, P1v * p2.z) + fmaxf(E1v * e2.w, P1v * p2.w);
        }
        smem[OFF_DENP + half * 128 + vv] = den;
    }
    __syncthreads();
    if (tid < 128) {
        float den = smem[OFF_DENP + tid] + smem[OFF_DENP + 128 + tid];
        float num = fmaxf(smem[OFF_E1 + tid] * smem[OFF_E2 + tid],
                          smem[OFF_P1 + tid] * smem[OFF_P2 + tid]);
        smem[OFF_DIAG + tid] = num / den;
    }
    __syncthreads();

    // ---- out[b][f][t][v] = elu(diag[v] * acc) ; 32B-contiguous STG.32 ----
    {
        float dg[4];
        #pragma unroll
        for (int k = 0; k < 4; k++)
            dg[k] = smem[OFF_DIAG + vbase + 16 * (k >> 1) + 8 * (k & 1) + g];
        #pragma unroll
        for (int i = 0; i < 2; i++) {
            const int v0 = vbase + 16 * i + g;
            #pragma unroll
            for (int j = 0; j < 4; j++) {
                const int f = fbase + 8 * j + 2 * ti;
                float* ob = out + ((size_t)(b * Fn + f) * Tn + t) * Vn;
                ob[v0]               = elu_fast(dg[2 * i]     * acc[i][j][0]);
                ob[Tn * Vn + v0]     = elu_fast(dg[2 * i]     * acc[i][j][1]);
                ob[v0 + 8]           = elu_fast(dg[2 * i + 1] * acc[i][j][2]);
                ob[Tn * Vn + v0 + 8] = elu_fast(dg[2 * i + 1] * acc[i][j][3]);
            }
        }
    }
}

extern "C" void kernel_launch(void* const* d_in, const int* in_sizes, int n_in,
                              void* d_out, int out_size)
{
    const float* x = (const float*)d_in[0];
    const float* W = (const float*)d_in[1];
    const float* a = (const float*)d_in[2];
    float* out = (float*)d_out;

    cudaFuncSetAttribute(GraphAttentionLayer4D_78082505441863_kernel,
                         cudaFuncAttributeMaxDynamicSharedMemorySize,
                         SMEM_FLOATS * (int)sizeof(float));

    prep_kernel<<<1, 256>>>(W);

    dim3 grid(Tn, Bn);   // one CTA per (t, b): 2048 CTAs
    GraphAttentionLayer4D_78082505441863_kernel
        <<<grid, 256, SMEM_FLOATS * sizeof(float)>>>(x, a, out);
}

// round 15
// speedup vs baseline: 1.1446x; 1.0148x over previous
#include <cuda_runtime.h>

// out[b][f][t][v] = elu(diag[b,v,t] * Wh[b,v,t,f])
//   Wh[b,v,t,f] = sum_c x[b,c,t,v] * W[c,f]      <-- mma.sync bf16 3-pass split
//   s1[v] = Wh[v,:]·a1 ; s2[v] = Wh[v,:]·a2       (per b,t)
//   diag[v] = num(v) / sum_j max(E1[v]E2[j], P1[v]P2[j])   (factorized leaky-softmax)

#define ALPHA 0.2f
#define LOG2E 1.4426950408889634f
constexpr int Bn = 8, Cn = 64, Tn = 256, Vn = 128, Fn = 64;

__device__ __forceinline__ unsigned smem_u32(const void* p) {
    unsigned a;
    asm("{ .reg .u64 t; cvta.to.shared.u64 t, %1; cvt.u32.u64 %0, t; }" : "=r"(a) : "l"(p));
    return a;
}
// pack two f32 -> bf16x2 (rn): result[15:0]=first arg, [31:16]=second arg
__device__ __forceinline__ unsigned pack_bf16(float lo_elem, float hi_elem) {
    unsigned r;
    asm("cvt.rn.bf16x2.f32 %0, %1, %2;" : "=r"(r) : "f"(hi_elem), "f"(lo_elem));
    return r;
}
__device__ __forceinline__ void ldsm4(unsigned* r, unsigned addr) {
    asm volatile("ldmatrix.sync.aligned.m8n8.x4.shared.b16 {%0,%1,%2,%3}, [%4];"
                 : "=r"(r[0]), "=r"(r[1]), "=r"(r[2]), "=r"(r[3]) : "r"(addr));
}
__device__ __forceinline__ void mma_bf16(float* c, const unsigned* a, const unsigned* b) {
    asm volatile(
        "mma.sync.aligned.m16n8k16.row.col.f32.bf16.bf16.f32 "
        "{%0,%1,%2,%3}, {%4,%5,%6,%7}, {%8,%9}, {%0,%1,%2,%3};"
        : "+f"(c[0]), "+f"(c[1]), "+f"(c[2]), "+f"(c[3])
        : "r"(a[0]), "r"(a[1]), "r"(a[2]), "r"(a[3]), "r"(b[0]), "r"(b[1]));
}
__device__ __forceinline__ unsigned bf16_bits(float f) {   // rn f32->bf16 bits
    unsigned u = __float_as_uint(f);
    return (u + 0x7FFFu + ((u >> 16) & 1u)) >> 16;
}
// branchless ELU: r>0 -> r ; small-neg -> cubic ; else exp2-based
__device__ __forceinline__ float elu_fast(float r) {
    float em  = exp2f(r * LOG2E) - 1.0f;
    float pl  = r * fmaf(r, fmaf(r, 0.16666667f, 0.5f), 1.0f);
    float neg = (r > -0.03125f) ? pl : em;
    return (r > 0.f) ? r : neg;
}

// ---- B-fragment table: [wn(2)][ks(4)][ph(4: hi-h0, hi-h1, lo-h0, lo-h1)][lane(32)] ----
__device__ uint4 g_Btab[2 * 4 * 4 * 32];

__global__ __launch_bounds__(256) void prep_kernel(const float* __restrict__ W) {
    __shared__ unsigned char ps[16384];   // WT hi [0,8K), WT lo [8K,16K)
    const int tid = threadIdx.x;

    for (int idx = tid; idx < Fn * Cn; idx += 256) {
        int f = idx >> 6, c = idx & 63;
        float w = W[c * Fn + f];
        unsigned hb = bf16_bits(w);
        float lo = w - __uint_as_float(hb << 16);
        unsigned lb = bf16_bits(lo);
        unsigned off = f * 128 + ((2 * c) ^ ((f & 7) << 4));
        *(unsigned short*)(ps + off)        = (unsigned short)hb;
        *(unsigned short*)(ps + 8192 + off) = (unsigned short)lb;
    }
    __syncthreads();

    if (tid < 32) {
        const unsigned lane = tid, q = lane >> 3, r = lane & 7;
        const unsigned sb = smem_u32(ps);
        for (int wn = 0; wn < 2; wn++) {
            const unsigned rB  = wn * 32 + (q >> 1) * 8 + r;
            const unsigned swB = (rB & 7) << 4;
            const unsigned rowb = rB * 128;
            for (int ks = 0; ks < 4; ks++) {
                const unsigned cB = (32 * ks + (q & 1) * 16) ^ swB;
                unsigned bx[4];
                const int base = ((wn * 4 + ks) * 4) * 32 + lane;
                ldsm4(bx, sb + rowb + cB);
                g_Btab[base]      = make_uint4(bx[0], bx[1], bx[2], bx[3]);
                ldsm4(bx, sb + 2048 + rowb + cB);
                g_Btab[base + 32] = make_uint4(bx[0], bx[1], bx[2], bx[3]);
                ldsm4(bx, sb + 8192 + rowb + cB);
                g_Btab[base + 64] = make_uint4(bx[0], bx[1], bx[2], bx[3]);
                ldsm4(bx, sb + 8192 + 2048 + rowb + cB);
                g_Btab[base + 96] = make_uint4(bx[0], bx[1], bx[2], bx[3]);
            }
        }
    }
}

// ---- smem layout (float offsets) ----
#define OFF_A1    0      // 64
#define OFF_A2    64     // 64
#define OFF_E1    128    // 128  exp(s1)
#define OFF_P1    256    // 128  exp(0.2 s1)
#define OFF_E2    384    // 128  exp(s2)
#define OFF_P2    512    // 128  exp(0.2 s2)
#define OFF_S1P   640    // [2][128]
#define OFF_S2P   896    // [2][128]
#define OFF_DENP  1152   // [2][128]
#define OFF_DIAG  1408   // 128
#define OFF_AHI   1536   // 16KB: A_hi [v=128][c=64] bf16 swizzled
#define OFF_ALO   5632   // 16KB
// Whs overlays A-tiles after MMA: 64 rows x 132-word padded stride (bank-safe)
#define OFF_WHS   1536
#define WHS_STRIDE 132
#define SMEM_FLOATS 9984    // 39,936 B -> 4 CTAs/SM (reg-capped anyway)

extern __shared__ float smem[];

__global__ __launch_bounds__(256, 4)
void GraphAttentionLayer4D_78082505441863_kernel(
    const float* __restrict__ x, const float* __restrict__ a,
    float* __restrict__ out)
{
    const int t    = blockIdx.x;
    const int b    = blockIdx.y;
    const int tid  = threadIdx.x;
    const int wid  = tid >> 5, lane = tid & 31;
    const int g    = lane >> 2, ti = lane & 3;   // mma quad layout
    const unsigned sbase = smem_u32(smem);

    if (tid < 128) {
        float av = a[tid];
        if (tid < 64) smem[OFF_A1 + tid] = av;
        else          smem[OFF_A2 + tid - 64] = av;
    }

    // ---- fused load+split: x[b,c,t,v] -> A_hi/A_lo [v][c] bf16 swizzled ----
    {
        const int v  = tid & 127;
        const int c0 = (tid >> 7) << 5;
        const float* xp = x + ((size_t)b * Cn + c0) * (size_t)(Tn * Vn)
                            + (size_t)t * Vn + v;
        float xr[32];
        #pragma unroll
        for (int k = 0; k < 32; k++)
            xr[k] = xp[(size_t)k * (Tn * Vn)];

        char* Ahi = (char*)smem + OFF_AHI * 4 + v * 128;
        char* Alo = (char*)smem + OFF_ALO * 4 + v * 128;
        const unsigned sw = (v & 7) << 4;
        #pragma unroll
        for (int m = 0; m < 4; m++) {
            const float* xc = xr + 8 * m;
            unsigned h0 = pack_bf16(xc[0], xc[1]);
            unsigned h1 = pack_bf16(xc[2], xc[3]);
            unsigned h2 = pack_bf16(xc[4], xc[5]);
            unsigned h3 = pack_bf16(xc[6], xc[7]);
            float l0 = xc[0] - __uint_as_float(h0 << 16);
            float l1 = xc[1] - __uint_as_float(h0 & 0xFFFF0000u);
            float l2 = xc[2] - __uint_as_float(h1 << 16);
            float l3 = xc[3] - __uint_as_float(h1 & 0xFFFF0000u);
            float l4 = xc[4] - __uint_as_float(h2 << 16);
            float l5 = xc[5] - __uint_as_float(h2 & 0xFFFF0000u);
            float l6 = xc[6] - __uint_as_float(h3 << 16);
            float l7 = xc[7] - __uint_as_float(h3 & 0xFFFF0000u);
            unsigned q0 = pack_bf16(l0, l1);
            unsigned q1 = pack_bf16(l2, l3);
            unsigned q2 = pack_bf16(l4, l5);
            unsigned q3 = pack_bf16(l6, l7);
            unsigned off = (unsigned)(2 * (c0 + 8 * m)) ^ sw;   // 16B-aligned
            *(uint4*)(Ahi + off) = make_uint4(h0, h1, h2, h3);
            *(uint4*)(Alo + off) = make_uint4(q0, q1, q2, q3);
        }
    }
    __syncthreads();

    // ---- MMA mainloop: A via ldsm (each tile read once), B via LDG frag table ----
    const int wm = wid & 3, wn = wid >> 2;
    const int vbase = wm * 32, fbase = wn * 32;

    const unsigned q = lane >> 3, r = lane & 7;
    const unsigned rA  = vbase + (q & 1) * 8 + r;
    const unsigned cAq = (q >> 1) * 16;
    const unsigned swA = (rA & 7) << 4;

    const unsigned pAhi = sbase + OFF_AHI * 4 + rA * 128;
    const unsigned pAlo = sbase + OFF_ALO * 4 + rA * 128;
    const uint4* __restrict__ btb = g_Btab + wn * 512 + lane;

    float acc[2][4][4];
    #pragma unroll
    for (int i = 0; i < 2; i++)
        #pragma unroll
        for (int j = 0; j < 4; j++)
            #pragma unroll
            for (int e = 0; e < 4; e++) acc[i][j][e] = 0.f;

    #pragma unroll
    for (int ks = 0; ks < 4; ks++) {
        const unsigned cA = (32 * ks + cAq) ^ swA;
        unsigned ax[8], al[8];
        ldsm4(ax,     pAhi + cA);
        ldsm4(ax + 4, pAhi + 2048 + cA);
        ldsm4(al,     pAlo + cA);
        ldsm4(al + 4, pAlo + 2048 + cA);

        uint4 bq;
        bq = __ldg(btb + ks * 128);          // B-hi, n-half 0
        mma_bf16(acc[0][0], ax,     &bq.x); mma_bf16(acc[0][1], ax,     &bq.z);
        mma_bf16(acc[1][0], ax + 4, &bq.x); mma_bf16(acc[1][1], ax + 4, &bq.z);
        mma_bf16(acc[0][0], al,     &bq.x); mma_bf16(acc[0][1], al,     &bq.z);
        mma_bf16(acc[1][0], al + 4, &bq.x); mma_bf16(acc[1][1], al + 4, &bq.z);
        bq = __ldg(btb + ks * 128 + 32);     // B-hi, n-half 1
        mma_bf16(acc[0][2], ax,     &bq.x); mma_bf16(acc[0][3], ax,     &bq.z);
        mma_bf16(acc[1][2], ax + 4, &bq.x); mma_bf16(acc[1][3], ax + 4, &bq.z);
        mma_bf16(acc[0][2], al,     &bq.x); mma_bf16(acc[0][3], al,     &bq.z);
        mma_bf16(acc[1][2], al + 4, &bq.x); mma_bf16(acc[1][3], al + 4, &bq.z);
        bq = __ldg(btb + ks * 128 + 64);     // B-lo, n-half 0 (pairs with A-hi only)
        mma_bf16(acc[0][0], ax,     &bq.x); mma_bf16(acc[0][1], ax,     &bq.z);
        mma_bf16(acc[1][0], ax + 4, &bq.x); mma_bf16(acc[1][1], ax + 4, &bq.z);
        bq = __ldg(btb + ks * 128 + 96);     // B-lo, n-half 1
        mma_bf16(acc[0][2], ax,     &bq.x); mma_bf16(acc[0][3], ax,     &bq.z);
        mma_bf16(acc[1][2], ax + 4, &bq.x); mma_bf16(acc[1][3], ax + 4, &bq.z);
    }

    // Accumulator element (i,j,e): v = vbase+16i+g+8*(e>>1), f = fbase+8j+2ti+(e&1)

    // ---- s1/s2 partials from accumulators + quad butterfly reduce ----
    {
        float s1r[4] = {0.f, 0.f, 0.f, 0.f};
        float s2r[4] = {0.f, 0.f, 0.f, 0.f};
        #pragma unroll
        for (int j = 0; j < 4; j++) {
            float w1a = smem[OFF_A1 + fbase + 8 * j + 2 * ti];
            float w1b = smem[OFF_A1 + fbase + 8 * j + 2 * ti + 1];
            float w2a = smem[OFF_A2 + fbase + 8 * j + 2 * ti];
            float w2b = smem[OFF_A2 + fbase + 8 * j + 2 * ti + 1];
            #pragma unroll
            for (int i = 0; i < 2; i++) {
                s1r[2 * i]     += acc[i][j][0] * w1a + acc[i][j][1] * w1b;
                s1r[2 * i + 1] += acc[i][j][2] * w1a + acc[i][j][3] * w1b;
                s2r[2 * i]     += acc[i][j][0] * w2a + acc[i][j][1] * w2b;
                s2r[2 * i + 1] += acc[i][j][2] * w2a + acc[i][j][3] * w2b;
            }
        }
        #pragma unroll
        for (int k = 0; k < 4; k++) {
            s1r[k] += __shfl_xor_sync(0xFFFFFFFFu, s1r[k], 1);
            s1r[k] += __shfl_xor_sync(0xFFFFFFFFu, s1r[k], 2);
            s2r[k] += __shfl_xor_sync(0xFFFFFFFFu, s2r[k], 1);
            s2r[k] += __shfl_xor_sync(0xFFFFFFFFu, s2r[k], 2);
        }
        if (ti == 0) {
            #pragma unroll
            for (int k = 0; k < 4; k++)
                smem[OFF_S1P + wn * 128 + vbase + 16 * (k >> 1) + 8 * (k & 1) + g] = s1r[k];
        } else if (ti == 1) {
            #pragma unroll
            for (int k = 0; k < 4; k++)
                smem[OFF_S2P + wn * 128 + vbase + 16 * (k >> 1) + 8 * (k & 1) + g] = s2r[k];
        }
    }
    __syncthreads();   // all ldsm reads of A-tiles complete -> Whs overlay safe

    // ---- spill raw Wh to Whs[f][v] (padded stride; STS.32 conflict-free) ----
    {
        #pragma unroll
        for (int i = 0; i < 2; i++) {
            const int v0 = vbase + 16 * i + g;
            #pragma unroll
            for (int j = 0; j < 4; j++) {
                const int f0 = fbase + 8 * j + 2 * ti;
                float* wr0 = smem + OFF_WHS + f0 * WHS_STRIDE;
                float* wr1 = wr0 + WHS_STRIDE;
                wr0[v0]     = acc[i][j][0];
                wr1[v0]     = acc[i][j][1];
                wr0[v0 + 8] = acc[i][j][2];
                wr1[v0 + 8] = acc[i][j][3];
            }
        }
    }

    // ---- reduce + factorized exps: E = exp(s), P = exp(0.2 s) ----
    if (tid < 128) {
        float s1 = smem[OFF_S1P + tid] + smem[OFF_S1P + 128 + tid];
        smem[OFF_E1 + tid] = exp2f(s1 * LOG2E);
        smem[OFF_P1 + tid] = exp2f(s1 * (ALPHA * LOG2E));
    } else {
        int vv = tid - 128;
        float s2 = smem[OFF_S2P + vv] + smem[OFF_S2P + 128 + vv];
        smem[OFF_E2 + vv] = exp2f(s2 * LOG2E);
        smem[OFF_P2 + vv] = exp2f(s2 * (ALPHA * LOG2E));
    }
    __syncthreads();

    // ---- den[v] = sum_j max(E1[v]E2[j], P1[v]P2[j])  (pure FMA-pipe) ----
    {
        const int vv = tid & 127, half = tid >> 7;
        float E1v = smem[OFF_E1 + vv], P1v = smem[OFF_P1 + vv];
        float den = 0.f;
        const float4* E2q = (const float4*)(smem + OFF_E2) + half * 16;
        const float4* P2q = (const float4*)(smem + OFF_P2) + half * 16;
        #pragma unroll 8
        for (int j = 0; j < 16; j++) {
            float4 e2 = E2q[j];
            float4 p2 = P2q[j];
            den += fmaxf(E1v * e2.x, P1v * p2.x) + fmaxf(E1v * e2.y, P1v * p2.y)
                 + fmaxf(E1v * e2.z, P1v * p2.z) + fmaxf(E1v * e2.w, P1v * p2.w);
        }
        smem[OFF_DENP + half * 128 + vv] = den;
    }
    __syncthreads();
    if (tid < 128) {
        float den = smem[OFF_DENP + tid] + smem[OFF_DENP + 128 + tid];
        float num = fmaxf(smem[OFF_E1 + tid] * smem[OFF_E2 + tid],
                          smem[OFF_P1 + tid] * smem[OFF_P2 + tid]);
        smem[OFF_DIAG + tid] = num / den;
    }
    __syncthreads();

    // ---- out-copy: each warp streams full 512B rows; STG.128 fully coalesced ----
    {
        float4 dg4 = ((const float4*)(smem + OFF_DIAG))[lane];   // diag[4*lane ..]
        #pragma unroll
        for (int rr = 0; rr < 8; rr++) {
            const int f = 8 * wid + rr;
            float4 wv = *(const float4*)(smem + OFF_WHS + f * WHS_STRIDE + 4 * lane);
            float4 o;
            o.x = elu_fast(dg4.x * wv.x);
            o.y = elu_fast(dg4.y * wv.y);
            o.z = elu_fast(dg4.z * wv.z);
            o.w = elu_fast(dg4.w * wv.w);
            float* ob = out + ((size_t)(b * Fn + f) * Tn + t) * Vn;
            ((float4*)ob)[lane] = o;
        }
    }
}

extern "C" void kernel_launch(void* const* d_in, const int* in_sizes, int n_in,
                              void* d_out, int out_size)
{
    const float* x = (const float*)d_in[0];
    const float* W = (const float*)d_in[1];
    const float* a = (const float*)d_in[2];
    float* out = (float*)d_out;

    cudaFuncSetAttribute(GraphAttentionLayer4D_78082505441863_kernel,
                         cudaFuncAttributeMaxDynamicSharedMemorySize,
                         SMEM_FLOATS * (int)sizeof(float));

    prep_kernel<<<1, 256>>>(W);

    dim3 grid(Tn, Bn);   // one CTA per (t, b): 2048 CTAs
    GraphAttentionLayer4D_78082505441863_kernel
        <<<grid, 256, SMEM_FLOATS * sizeof(float)>>>(x, a, out);
}